// round 1
// baseline (speedup 1.0000x reference)
#include <cuda_runtime.h>
#include <cuda_bf16.h>

#define NN 50000
#define EE 800000
#define FIN 128
#define HH 8
#define CC 32
#define HC 256

__device__ float g_h[NN * HC];
__device__ float g_asrc[NN * HH];
__device__ float g_adst[NN * HH];
__device__ int   g_deg[NN];
__device__ int   g_rowptr[NN + 1];
__device__ int   g_src[EE];
__device__ int   g_eid[EE];
__device__ int   g_is64;

__global__ void detect_kernel(const void* ei) {
    const long long* p = (const long long*)ei;
    int ok = 1;
    for (int k = 0; k < 16; k++) {
        long long v = p[k];
        if (v < 0 || v >= NN) ok = 0;
    }
    g_is64 = ok;
}

__device__ __forceinline__ int edge_idx(const void* ei, long long k, int is64) {
    return is64 ? (int)((const long long*)ei)[k] : ((const int*)ei)[k];
}

#define BM 64
#define BN 64
#define BK 16
__global__ void gemm_kernel(const float* __restrict__ A, const float* __restrict__ B, int M) {
    __shared__ float As[BK][BM + 1];
    __shared__ float Bs[BK][BN];
    const int bm = blockIdx.x * BM, bn = blockIdx.y * BN;
    const int tid = threadIdx.x;
    const int tx = tid & 15, ty = tid >> 4;
    float acc[4][4] = {};
    for (int k0 = 0; k0 < FIN; k0 += BK) {
        #pragma unroll
        for (int l = 0; l < 4; l++) {
            int idx = tid + l * 256;
            int r = idx >> 4, c = idx & 15;
            int gr = bm + r;
            As[c][r] = (gr < M) ? A[(long long)gr * FIN + k0 + c] : 0.f;
        }
        #pragma unroll
        for (int l = 0; l < 4; l++) {
            int idx = tid + l * 256;
            int r = idx >> 6, c = idx & 63;
            Bs[r][c] = B[(k0 + r) * HC + bn + c];
        }
        __syncthreads();
        #pragma unroll
        for (int kk = 0; kk < BK; kk++) {
            float a[4];
            #pragma unroll
            for (int i = 0; i < 4; i++) a[i] = As[kk][ty * 4 + i];
            float4 b4 = *(const float4*)&Bs[kk][tx * 4];
            float b[4] = {b4.x, b4.y, b4.z, b4.w};
            #pragma unroll
            for (int i = 0; i < 4; i++)
                #pragma unroll
                for (int j = 0; j < 4; j++)
                    acc[i][j] += a[i] * b[j];
        }
        __syncthreads();
    }
    #pragma unroll
    for (int i = 0; i < 4; i++) {
        int gr = bm + ty * 4 + i;
        if (gr < M) {
            float4* dst = (float4*)&g_h[(long long)gr * HC + bn + tx * 4];
            *dst = make_float4(acc[i][0], acc[i][1], acc[i][2], acc[i][3]);
        }
    }
}

__global__ void scores_kernel(const float* __restrict__ att_src,
                              const float* __restrict__ att_dst, int n) {
    int w = (blockIdx.x * blockDim.x + threadIdx.x) >> 5;
    int lane = threadIdx.x & 31;
    if (w >= n * HH) return;
    int i = w / HH, hh = w % HH;
    float v = g_h[(long long)i * HC + hh * CC + lane];
    float s1 = v * att_src[hh * CC + lane];
    float s2 = v * att_dst[hh * CC + lane];
    #pragma unroll
    for (int o = 16; o > 0; o >>= 1) {
        s1 += __shfl_xor_sync(0xFFFFFFFFu, s1, o);
        s2 += __shfl_xor_sync(0xFFFFFFFFu, s2, o);
    }
    if (lane == 0) { g_asrc[w] = s1; g_adst[w] = s2; }
}

__global__ void zero_deg_kernel(int n) {
    int i = blockIdx.x * blockDim.x + threadIdx.x;
    if (i < n) g_deg[i] = 0;
}

__global__ void degree_kernel(const void* ei, int E) {
    int e = blockIdx.x * blockDim.x + threadIdx.x;
    if (e >= E) return;
    int d = edge_idx(ei, e, g_is64);
    atomicAdd(&g_deg[d], 1);
}

__global__ void scan_kernel(int n) {
    __shared__ int part[1024];
    int t = threadIdx.x;
    int chunk = (n + 1023) / 1024;
    int beg = t * chunk;
    int end = beg + chunk; if (end > n) end = n;
    int s = 0;
    for (int i = beg; i < end; i++) { g_rowptr[i] = s; s += g_deg[i]; }
    part[t] = s;
    __syncthreads();
    for (int off = 1; off < 1024; off <<= 1) {
        int v = (t >= off) ? part[t - off] : 0;
        __syncthreads();
        part[t] += v;
        __syncthreads();
    }
    int base = (t == 0) ? 0 : part[t - 1];
    for (int i = beg; i < end; i++) { g_rowptr[i] += base; g_deg[i] = 0; }
    if (t == 1023) g_rowptr[n] = part[1023];
}

__global__ void scatter_kernel(const void* ei, int E) {
    int e = blockIdx.x * blockDim.x + threadIdx.x;
    if (e >= E) return;
    int is64 = g_is64;
    int d = edge_idx(ei, e, is64);
    int s = edge_idx(ei, (long long)E + e, is64);
    int pos = atomicAdd(&g_deg[d], 1);
    int slot = g_rowptr[d] + pos;
    g_src[slot] = s;
    g_eid[slot] = e;
}

__global__ void agg_kernel(const float* __restrict__ dp,
                           const float* __restrict__ dp_self,
                           const float* __restrict__ bias,
                           float* __restrict__ out, int n) {
    int i = blockIdx.x;
    int hh = threadIdx.x >> 5;
    int c = threadIdx.x & 31;
    float adst_i = g_adst[i * HH + hh];
    float asrc_i = g_asrc[i * HH + hh];
    float hself = g_h[(long long)i * HC + hh * CC + c];
    float a0 = asrc_i + adst_i;
    a0 = a0 > 0.f ? a0 : 0.2f * a0;
    float m = a0;
    float s = 1.f;
    float acc = dp_self[i * HH + hh] * hself;
    int beg = g_rowptr[i], end = g_rowptr[i + 1];
    for (int slot = beg; slot < end; slot++) {
        int src = g_src[slot];
        int eid = g_eid[slot];
        float a = g_asrc[src * HH + hh] + adst_i;
        a = a > 0.f ? a : 0.2f * a;
        float hv = g_h[(long long)src * HC + hh * CC + c];
        float mk = dp[(long long)eid * HH + hh];
        float nm = fmaxf(m, a);
        float scale = __expf(m - nm);
        float w = __expf(a - nm);
        s = s * scale + w;
        acc = acc * scale + w * mk * hv;
        m = nm;
    }
    out[(long long)i * HC + hh * CC + c] = acc / s + bias[hh * CC + c];
}

extern "C" void kernel_launch(void* const* d_in, const int* in_sizes, int n_in,
                              void* d_out, int out_size) {
    const float* x       = (const float*)d_in[0];
    const void*  ei      = d_in[1];
    const float* dp      = (const float*)d_in[2];
    const float* dp_self = (const float*)d_in[3];
    const float* W       = (const float*)d_in[4];
    const float* att_src = (const float*)d_in[5];
    const float* att_dst = (const float*)d_in[6];
    const float* bias    = (const float*)d_in[7];
    float* out = (float*)d_out;

    int n = in_sizes[0] / FIN;   // 50000
    int E = in_sizes[2] / HH;    // 800000 (dtype-independent derivation)

    detect_kernel<<<1, 1>>>(ei);

    dim3 ggrid((n + BM - 1) / BM, HC / BN);
    gemm_kernel<<<ggrid, 256>>>(x, W, n);

    scores_kernel<<<(n * HH * 32 + 255) / 256, 256>>>(att_src, att_dst, n);

    zero_deg_kernel<<<(n + 255) / 256, 256>>>(n);
    degree_kernel<<<(E + 255) / 256, 256>>>(ei, E);
    scan_kernel<<<1, 1024>>>(n);
    scatter_kernel<<<(E + 255) / 256, 256>>>(ei, E);

    agg_kernel<<<n, 256>>>(dp, dp_self, bias, out, n);
}

// round 2
// speedup vs baseline: 1.3160x; 1.3160x over previous
#include <cuda_runtime.h>
#include <cuda_bf16.h>

#define NN 50000
#define EE 800000
#define FIN 128
#define HH 8
#define CC 32
#define HC 256

__device__ float g_h[NN * HC];
__device__ float g_asrc[NN * HH];
__device__ float g_adst[NN * HH];
__device__ int   g_deg[NN];
__device__ int   g_rowptr[NN + 1];
__device__ int   g_src[EE];
__device__ int   g_eid[EE];
__device__ int   g_is64;

// ---------------- init: zero degree counters + detect edge_index dtype --------
__global__ void init_kernel(const void* ei, int n) {
    int i = blockIdx.x * blockDim.x + threadIdx.x;
    if (i < n) g_deg[i] = 0;
    if (i == 0) {
        const long long* p = (const long long*)ei;
        int ok = 1;
        for (int k = 0; k < 16; k++) {
            long long v = p[k];
            if (v < 0 || v >= NN) ok = 0;
        }
        g_is64 = ok;
    }
}

__device__ __forceinline__ int edge_idx(const void* ei, long long k, int is64) {
    return is64 ? (int)((const long long*)ei)[k] : ((const int*)ei)[k];
}

// ---------------- SGEMM 128x128x8 with packed f32x2 FMA ----------------
__device__ __forceinline__ void ffma2(unsigned long long& d,
                                      unsigned long long a,
                                      unsigned long long b) {
    asm("fma.rn.f32x2 %0, %1, %2, %0;" : "+l"(d) : "l"(a), "l"(b));
}
__device__ __forceinline__ unsigned long long dup2(float x) {
    unsigned long long r;
    unsigned int u = __float_as_uint(x);
    asm("mov.b64 %0, {%1, %1};" : "=l"(r) : "r"(u));
    return r;
}

__global__ __launch_bounds__(256, 2)
void gemm_kernel(const float* __restrict__ A, const float* __restrict__ B, int M) {
    __shared__ float As[8][128];
    __shared__ float Bs[8][128];
    const int tid = threadIdx.x;
    const int bm = blockIdx.x * 128;
    const int bn = blockIdx.y * 128;
    // loaders
    const int ar = tid >> 1, ak = (tid & 1) << 2;       // A: 128 rows x 8 k
    const int br = tid >> 5, bc = (tid & 31) << 2;      // B: 8 k x 128 n
    // compute mapping: rows {ty4+i, ty4+64+i}, cols {tx4+j, tx4+64+j}
    const int ty4 = (tid >> 4) << 2;
    const int tx4 = (tid & 15) << 2;

    unsigned long long acc[8][4];
    #pragma unroll
    for (int i = 0; i < 8; i++)
        #pragma unroll
        for (int j = 0; j < 4; j++) acc[i][j] = 0ull;

    for (int k0 = 0; k0 < FIN; k0 += 8) {
        float4 av = make_float4(0.f, 0.f, 0.f, 0.f);
        if (bm + ar < M) av = *(const float4*)&A[(size_t)(bm + ar) * FIN + k0 + ak];
        As[ak + 0][ar] = av.x;
        As[ak + 1][ar] = av.y;
        As[ak + 2][ar] = av.z;
        As[ak + 3][ar] = av.w;
        *(float4*)&Bs[br][bc] = *(const float4*)&B[(size_t)(k0 + br) * HC + bn + bc];
        __syncthreads();
        #pragma unroll
        for (int kk = 0; kk < 8; kk++) {
            float a[8];
            *(float4*)&a[0] = *(const float4*)&As[kk][ty4];
            *(float4*)&a[4] = *(const float4*)&As[kk][64 + ty4];
            unsigned long long b2[4];
            b2[0] = *(const unsigned long long*)&Bs[kk][tx4];
            b2[1] = *(const unsigned long long*)&Bs[kk][tx4 + 2];
            b2[2] = *(const unsigned long long*)&Bs[kk][64 + tx4];
            b2[3] = *(const unsigned long long*)&Bs[kk][64 + tx4 + 2];
            unsigned long long a2[8];
            #pragma unroll
            for (int i = 0; i < 8; i++) a2[i] = dup2(a[i]);
            #pragma unroll
            for (int i = 0; i < 8; i++)
                #pragma unroll
                for (int j = 0; j < 4; j++) ffma2(acc[i][j], a2[i], b2[j]);
        }
        __syncthreads();
    }
    // epilogue: pairs along N are contiguous -> 8-byte stores
    #pragma unroll
    for (int i = 0; i < 8; i++) {
        int row = bm + ((i < 4) ? (ty4 + i) : (64 + ty4 + i - 4));
        if (row < M) {
            unsigned long long* o0 = (unsigned long long*)&g_h[(size_t)row * HC + bn + tx4];
            unsigned long long* o1 = (unsigned long long*)&g_h[(size_t)row * HC + bn + 64 + tx4];
            o0[0] = acc[i][0];
            o0[1] = acc[i][1];
            o1[0] = acc[i][2];
            o1[1] = acc[i][3];
        }
    }
}

// ---------------- attention scores ----------------
__global__ void scores_kernel(const float* __restrict__ att_src,
                              const float* __restrict__ att_dst, int n) {
    int w = (blockIdx.x * blockDim.x + threadIdx.x) >> 5;
    int lane = threadIdx.x & 31;
    if (w >= n * HH) return;
    int i = w / HH, hh = w % HH;
    float v = g_h[(size_t)i * HC + hh * CC + lane];
    float s1 = v * att_src[hh * CC + lane];
    float s2 = v * att_dst[hh * CC + lane];
    #pragma unroll
    for (int o = 16; o > 0; o >>= 1) {
        s1 += __shfl_xor_sync(0xFFFFFFFFu, s1, o);
        s2 += __shfl_xor_sync(0xFFFFFFFFu, s2, o);
    }
    if (lane == 0) { g_asrc[w] = s1; g_adst[w] = s2; }
}

// ---------------- CSR build ----------------
__global__ void degree_kernel(const void* ei, int E) {
    int e = blockIdx.x * blockDim.x + threadIdx.x;
    if (e >= E) return;
    int d = edge_idx(ei, e, g_is64);
    atomicAdd(&g_deg[d], 1);
}

__global__ void scan_kernel(int n) {
    __shared__ int part[1024];
    int t = threadIdx.x;
    int chunk = (n + 1023) / 1024;
    int beg = t * chunk;
    int end = beg + chunk; if (end > n) end = n;
    int s = 0;
    for (int i = beg; i < end; i++) { g_rowptr[i] = s; s += g_deg[i]; }
    part[t] = s;
    __syncthreads();
    for (int off = 1; off < 1024; off <<= 1) {
        int v = (t >= off) ? part[t - off] : 0;
        __syncthreads();
        part[t] += v;
        __syncthreads();
    }
    int base = (t == 0) ? 0 : part[t - 1];
    for (int i = beg; i < end; i++) { g_rowptr[i] += base; g_deg[i] = 0; }
    if (t == 1023) g_rowptr[n] = part[1023];
}

__global__ void scatter_kernel(const void* ei, int E) {
    int e = blockIdx.x * blockDim.x + threadIdx.x;
    if (e >= E) return;
    int is64 = g_is64;
    int d = edge_idx(ei, e, is64);
    int s = edge_idx(ei, (long long)E + e, is64);
    int pos = atomicAdd(&g_deg[d], 1);
    int slot = g_rowptr[d] + pos;
    g_src[slot] = s;
    g_eid[slot] = e;
}

// ---------------- fused softmax + aggregate, chunked two-phase ----------------
#define CHUNK 64
__global__ void agg_kernel(const float* __restrict__ dp,
                           const float* __restrict__ dp_self,
                           const float* __restrict__ bias,
                           float* __restrict__ out, int n) {
    __shared__ float sw[CHUNK][9];   // pad 9: conflict-free STS
    __shared__ int ssrc[CHUNK];
    const int i = blockIdx.x;
    const int hh = threadIdx.x >> 5;
    const int lane = threadIdx.x & 31;

    const float adst_i = g_adst[i * HH + hh];
    float a0 = g_asrc[i * HH + hh] + adst_i;
    a0 = a0 > 0.f ? a0 : 0.2f * a0;
    float m = a0;                                   // running max
    float s = 1.f;                                  // running denom (exp(a0-m)=1)
    float acc = dp_self[i * HH + hh] * g_h[(size_t)i * HC + hh * CC + lane];

    const int beg = g_rowptr[i], end = g_rowptr[i + 1];
    for (int cb = beg; cb < end; cb += CHUNK) {
        const int L = min(end - cb, CHUNK);
        // ---- phase A: lanes over edges ----
        float aa[2], mk[2];
        float mc = -1e30f;
        #pragma unroll
        for (int j = 0; j < 2; j++) {
            int u = lane + j * 32;
            aa[j] = -1e30f; mk[j] = 0.f;
            if (u < L) {
                int slot = cb + u;
                int src = g_src[slot];
                if (hh == 0) ssrc[u] = src;
                int eid = g_eid[slot];
                float a = g_asrc[src * HH + hh] + adst_i;
                a = a > 0.f ? a : 0.2f * a;
                aa[j] = a;
                mk[j] = dp[(size_t)eid * HH + hh];
                mc = fmaxf(mc, a);
            }
        }
        #pragma unroll
        for (int o = 16; o > 0; o >>= 1) mc = fmaxf(mc, __shfl_xor_sync(0xFFFFFFFFu, mc, o));
        float nm = fmaxf(m, mc);
        float scale = __expf(m - nm);
        float sc = 0.f;
        #pragma unroll
        for (int j = 0; j < 2; j++) {
            int u = lane + j * 32;
            if (u < L) {
                float w = __expf(aa[j] - nm);
                sc += w;
                sw[u][hh] = w * mk[j];              // dropout applied post-normalization
            }
        }
        #pragma unroll
        for (int o = 16; o > 0; o >>= 1) sc += __shfl_xor_sync(0xFFFFFFFFu, sc, o);
        s = s * scale + sc;
        m = nm;
        __syncthreads();
        // ---- phase B: lanes over channels, independent gathers ----
        acc *= scale;
        float p1 = 0.f, p2 = 0.f, p3 = 0.f;
        int l = 0;
        for (; l + 3 < L; l += 4) {
            acc += sw[l + 0][hh] * g_h[(size_t)ssrc[l + 0] * HC + hh * CC + lane];
            p1  += sw[l + 1][hh] * g_h[(size_t)ssrc[l + 1] * HC + hh * CC + lane];
            p2  += sw[l + 2][hh] * g_h[(size_t)ssrc[l + 2] * HC + hh * CC + lane];
            p3  += sw[l + 3][hh] * g_h[(size_t)ssrc[l + 3] * HC + hh * CC + lane];
        }
        for (; l < L; l++)
            acc += sw[l][hh] * g_h[(size_t)ssrc[l] * HC + hh * CC + lane];
        acc += (p1 + p2) + p3;
        __syncthreads();
    }
    out[(size_t)i * HC + hh * CC + lane] = acc / s + bias[hh * CC + lane];
}

// ---------------- launcher ----------------
extern "C" void kernel_launch(void* const* d_in, const int* in_sizes, int n_in,
                              void* d_out, int out_size) {
    const float* x       = (const float*)d_in[0];
    const void*  ei      = d_in[1];
    const float* dp      = (const float*)d_in[2];
    const float* dp_self = (const float*)d_in[3];
    const float* W       = (const float*)d_in[4];
    const float* att_src = (const float*)d_in[5];
    const float* att_dst = (const float*)d_in[6];
    const float* bias    = (const float*)d_in[7];
    float* out = (float*)d_out;

    int n = in_sizes[0] / FIN;   // 50000
    int E = in_sizes[2] / HH;    // 800000 (dtype-independent)

    init_kernel<<<(n + 255) / 256, 256>>>(ei, n);

    dim3 ggrid((n + 127) / 128, HC / 128);
    gemm_kernel<<<ggrid, 256>>>(x, W, n);

    scores_kernel<<<(n * HH * 32 + 255) / 256, 256>>>(att_src, att_dst, n);

    degree_kernel<<<(E + 255) / 256, 256>>>(ei, E);
    scan_kernel<<<1, 1024>>>(n);
    scatter_kernel<<<(E + 255) / 256, 256>>>(ei, E);

    agg_kernel<<<n, 256>>>(dp, dp_self, bias, out, n);
}